// round 16
// baseline (speedup 1.0000x reference)
#include <cuda_runtime.h>
#include <cuda_fp16.h>
#include <mma.h>
using namespace nvcuda;

// ---------------- problem constants ----------------
#define NMAX 50000
#define EMAX 1600000
#define KDIM 128

// ---------------- device scratch ----------------
__device__ unsigned long long g_degc[NMAX];  // bits 44+: cnt, bits 0..43: ew-sum (2^-32 fixed)
__device__ float  g_dinv[NMAX];
__device__ int    g_cnt [NMAX];
__device__ int    g_off [NMAX];
__device__ int    g_rank[EMAX];
__device__ int2   g_csr [EMAX];              // (src, norm-as-bits), bucketed by dst
__device__ unsigned g_agg[256];              // lookback state: bit31 flag | aggregate
__device__ int    g_is64;
__device__ uint4  g_a16 [NMAX * KDIM / 8];   // fp16 activations (GEMM input)
__device__ uint4  g_hh  [NMAX * KDIM / 8];   // fp16 GEMM output (gather input)
__device__ uint4  g_w16 [5120];              // fp16 W1(2048) W2(2048) W3(1024)

// ---------------- fused init + dtype detect ----------------
__global__ void k_init(const void* __restrict__ ei, int n) {
    int i = blockIdx.x * blockDim.x + threadIdx.x;
    if (i < n) g_degc[i] = 0ULL;
    if (i < 256) g_agg[i] = 0u;
    if (i == 0) {
        const long long* p = (const long long*)ei;
        int ok = 1;
#pragma unroll
        for (int t = 0; t < 16; t++) {
            long long v = p[t];
            if (v < 0 || v >= (long long)n) ok = 0;
        }
        g_is64 = ok;
    }
}

// ---------------- fp32 -> fp16 conversion ----------------
__device__ inline uint4 pack8(float4 a, float4 b) {
    __half2 h0 = __floats2half2_rn(a.x, a.y), h1 = __floats2half2_rn(a.z, a.w);
    __half2 h2 = __floats2half2_rn(b.x, b.y), h3 = __floats2half2_rn(b.z, b.w);
    uint4 u;
    u.x = *(unsigned*)&h0; u.y = *(unsigned*)&h1;
    u.z = *(unsigned*)&h2; u.w = *(unsigned*)&h3;
    return u;
}

__global__ void k_prep(const float4* __restrict__ x,
                       const float4* __restrict__ W1,
                       const float4* __restrict__ W2,
                       const float4* __restrict__ W3, int n) {
    int i = blockIdx.x * blockDim.x + threadIdx.x;
    int nx = n * 16;
    if (i < nx) {
        g_a16[i] = pack8(x[2 * i], x[2 * i + 1]);
    } else {
        int j = i - nx;
        if (j < 5120) {
            const float4* src; int jj;
            if (j < 2048)      { src = W1; jj = j; }
            else if (j < 4096) { src = W2; jj = j - 2048; }
            else               { src = W3; jj = j - 4096; }
            g_w16[j] = pack8(src[2 * jj], src[2 * jj + 1]);
        }
    }
}

// ---------------- edge pass 1: 2 edges/thread, 64-bit packed atomic ----------------
__global__ void k_edge_deg(const void* __restrict__ ei,
                           const float* __restrict__ ew, int E, int n) {
    int e = (blockIdx.x * blockDim.x + threadIdx.x) * 2;
    if (e >= E) return;
    int s0, d0, s1 = -1, d1 = -1;
    bool two = (e + 1 < E);
    if (g_is64) {
        const long long* p = (const long long*)ei;
        s0 = (int)p[e]; d0 = (int)p[E + e];
        if (two) { s1 = (int)p[e + 1]; d1 = (int)p[E + e + 1]; }
    } else {
        const int* p = (const int*)ei;
        int2 sv = *(const int2*)(p + e);
        int2 dv = *(const int2*)(p + E + e);
        s0 = sv.x; d0 = dv.x;
        if (two) { s1 = sv.y; d1 = dv.y; }
    }
    float2 wv = two ? *(const float2*)(ew + e) : make_float2(ew[e], 0.f);
    int r0 = -1, r1 = -1;
    if ((unsigned)s0 < (unsigned)n && (unsigned)d0 < (unsigned)n) {
        unsigned long long fx = (unsigned long long)((double)wv.x * 4294967296.0);
        r0 = (int)(atomicAdd(&g_degc[d0], (1ULL << 44) | fx) >> 44);
    }
    if (two) {
        if ((unsigned)s1 < (unsigned)n && (unsigned)d1 < (unsigned)n) {
            unsigned long long fx = (unsigned long long)((double)wv.y * 4294967296.0);
            r1 = (int)(atomicAdd(&g_degc[d1], (1ULL << 44) | fx) >> 44);
        }
        *(int2*)(g_rank + e) = make_int2(r0, r1);
    } else {
        g_rank[e] = r0;
    }
}

// ---------------- single-kernel scan (decode degc -> dinv/cnt, lookback -> off) ----------------
__global__ void k_scan(int n) {
    __shared__ int s[512];
    __shared__ int base;
    const int t = threadIdx.x, b = blockIdx.x, i = b * 512 + t;
    int c = 0;
    if (i < n) {
        unsigned long long v = g_degc[i];
        float wsum = (float)((double)(v & ((1ULL << 44) - 1)) * (1.0 / 4294967296.0));
        g_dinv[i] = rsqrtf(wsum + 1.0f);          // +1 self-loop weight
        c = (int)(v >> 44);
        g_cnt[i] = c;
    }
    s[t] = c;
    __syncthreads();
    for (int st = 1; st < 512; st <<= 1) {
        int add = (t >= st) ? s[t - st] : 0;
        __syncthreads();
        s[t] += add;
        __syncthreads();
    }
    if (t == 511) atomicExch(&g_agg[b], 0x80000000u | (unsigned)s[511]);
    if (t == 0) base = 0;
    __syncthreads();
    int partial = 0;
    for (int j = t; j < b; j += 512) {
        unsigned v;
        do { v = atomicAdd(&g_agg[j], 0u); } while (!(v & 0x80000000u));
        partial += (int)(v & 0x7fffffffu);
    }
    if (partial) atomicAdd(&base, partial);
    __syncthreads();
    if (i < n) g_off[i] = base + s[t] - c;
}

// ---------------- edge pass 2: fill CSR (no atomics) ----------------
__global__ void k_edge_fill(const void* __restrict__ ei,
                            const float* __restrict__ ew, int E) {
    int e = (blockIdx.x * blockDim.x + threadIdx.x) * 2;
    if (e >= E) return;
    bool two = (e + 1 < E);
    int2 rr = two ? *(const int2*)(g_rank + e) : make_int2(g_rank[e], -1);
    int s0, d0, s1 = 0, d1 = 0;
    if (g_is64) {
        const long long* p = (const long long*)ei;
        s0 = (int)p[e]; d0 = (int)p[E + e];
        if (two) { s1 = (int)p[e + 1]; d1 = (int)p[E + e + 1]; }
    } else {
        const int* p = (const int*)ei;
        int2 sv = *(const int2*)(p + e);
        int2 dv = *(const int2*)(p + E + e);
        s0 = sv.x; d0 = dv.x; s1 = sv.y; d1 = dv.y;
    }
    float2 wv = two ? *(const float2*)(ew + e) : make_float2(ew[e], 0.f);
    if (rr.x >= 0) {
        float nrm = g_dinv[s0] * wv.x * g_dinv[d0];
        g_csr[g_off[d0] + rr.x] = make_int2(s0, __float_as_int(nrm));
    }
    if (two && rr.y >= 0) {
        float nrm = g_dinv[s1] * wv.y * g_dinv[d1];
        g_csr[g_off[d1] + rr.y] = make_int2(s1, __float_as_int(nrm));
    }
}

// ---------------- tensor-core GEMM: C[M,N] = A16[M,128] @ W16[128,N] ----------------
template<int N>
__global__ void __launch_bounds__(256)
k_hgemm(int woff_u4, int M) {
    constexpr int BM  = 64;
    constexpr int LDA = 136;
    constexpr int WN  = N / 2;
    constexpr int NT  = WN / 16;
    constexpr int ABYTES = BM * LDA * 2;
    constexpr int SBYTES = 8 * 16 * WN * 4;
    __shared__ __align__(16) char sraw[(ABYTES > SBYTES) ? ABYTES : SBYTES];
    __half (*As)[LDA] = (__half(*)[LDA])sraw;
    float*  stage     = (float*)sraw;

    const __half* Wg = (const __half*)g_w16 + (long)woff_u4 * 8;

    const int tid  = threadIdx.x;
    const int wid  = tid >> 5, lane = tid & 31;
    const int wrow = wid >> 1, wcol = wid & 1;
    const int rb   = blockIdx.x * BM;

    for (int i = tid; i < BM * 16; i += 256) {
        int r = i >> 4, c = i & 15;
        uint4 v = make_uint4(0u, 0u, 0u, 0u);
        if (rb + r < M) v = g_a16[(long)(rb + r) * 16 + c];
        *(uint4*)&As[r][c * 8] = v;
    }
    __syncthreads();

    wmma::fragment<wmma::accumulator, 16, 16, 16, float> acc[NT];
#pragma unroll
    for (int j = 0; j < NT; j++) wmma::fill_fragment(acc[j], 0.0f);

    wmma::fragment<wmma::matrix_a, 16, 16, 16, __half, wmma::row_major> af;
    wmma::fragment<wmma::matrix_b, 16, 16, 16, __half, wmma::row_major> bf;
#pragma unroll
    for (int k = 0; k < 8; k++) {
        wmma::load_matrix_sync(af, &As[wrow * 16][k * 16], LDA);
#pragma unroll
        for (int j = 0; j < NT; j++) {
            wmma::load_matrix_sync(bf, Wg + (long)(k * 16) * N + wcol * WN + j * 16, N);
            wmma::mma_sync(acc[j], af, bf, acc[j]);
        }
    }
    __syncthreads();

    float* st = stage + wid * 16 * WN;
#pragma unroll
    for (int j = 0; j < NT; j++)
        wmma::store_matrix_sync(st + j * 16, acc[j], WN, wmma::mem_row_major);
    __syncwarp();

    const int r0 = rb + wrow * 16;
    unsigned* outh = (unsigned*)g_hh;
    for (int i = lane; i < 16 * WN / 2; i += 32) {
        int r = (i * 2) / WN, c = (i * 2) % WN;
        int gr = r0 + r;
        if (gr < M) {
            __half2 h = __floats2half2_rn(st[r * WN + c], st[r * WN + c + 1]);
            outh[((long)gr * N + wcol * WN + c) >> 1] = *(unsigned*)&h;
        }
    }
}

// ---------------- fp16 row math helpers ----------------
__device__ inline void fma8(const uint4& hv, float nrm, float* a) {
    __half2 h0 = *(__half2*)&hv.x, h1 = *(__half2*)&hv.y;
    __half2 h2 = *(__half2*)&hv.z, h3 = *(__half2*)&hv.w;
    float2 f0 = __half22float2(h0), f1 = __half22float2(h1);
    float2 f2 = __half22float2(h2), f3 = __half22float2(h3);
    a[0] = fmaf(f0.x, nrm, a[0]); a[1] = fmaf(f0.y, nrm, a[1]);
    a[2] = fmaf(f1.x, nrm, a[2]); a[3] = fmaf(f1.y, nrm, a[3]);
    a[4] = fmaf(f2.x, nrm, a[4]); a[5] = fmaf(f2.y, nrm, a[5]);
    a[6] = fmaf(f3.x, nrm, a[6]); a[7] = fmaf(f3.y, nrm, a[7]);
}

__device__ inline void scale8(const uint4& hv, float sl, float* a) {
    __half2 h0 = *(__half2*)&hv.x, h1 = *(__half2*)&hv.y;
    __half2 h2 = *(__half2*)&hv.z, h3 = *(__half2*)&hv.w;
    float2 f0 = __half22float2(h0), f1 = __half22float2(h1);
    float2 f2 = __half22float2(h2), f3 = __half22float2(h3);
    a[0] = f0.x * sl; a[1] = f0.y * sl; a[2] = f1.x * sl; a[3] = f1.y * sl;
    a[4] = f2.x * sl; a[5] = f2.y * sl; a[6] = f3.x * sl; a[7] = f3.y * sl;
}

__device__ inline void epilogue128(float* a, const float* bias, int sub, int node) {
    float4 b0 = *(const float4*)(bias + sub * 8);
    float4 b1 = *(const float4*)(bias + sub * 8 + 4);
    float rx0 = fmaxf(a[0] + b0.x, 0.f), rx1 = fmaxf(a[1] + b0.y, 0.f);
    float rx2 = fmaxf(a[2] + b0.z, 0.f), rx3 = fmaxf(a[3] + b0.w, 0.f);
    float rx4 = fmaxf(a[4] + b1.x, 0.f), rx5 = fmaxf(a[5] + b1.y, 0.f);
    float rx6 = fmaxf(a[6] + b1.z, 0.f), rx7 = fmaxf(a[7] + b1.w, 0.f);
    __half2 p0 = __floats2half2_rn(rx0, rx1), p1 = __floats2half2_rn(rx2, rx3);
    __half2 p2 = __floats2half2_rn(rx4, rx5), p3 = __floats2half2_rn(rx6, rx7);
    uint4 u;
    u.x = *(unsigned*)&p0; u.y = *(unsigned*)&p1;
    u.z = *(unsigned*)&p2; u.w = *(unsigned*)&p3;
    g_a16[(long)node * 16 + sub] = u;
}

// ---------------- gather F=128: half-warp handles TWO nodes (4 streams/warp) ----------------
__global__ void __launch_bounds__(256) k_gather_h(const float* __restrict__ bias, int n) {
    const int gt  = blockIdx.x * blockDim.x + threadIdx.x;
    const int grp = gt >> 4;             // half-warp group
    const int sub = gt & 15;             // lane owns features 8*sub .. 8*sub+7
    const int n0  = grp * 2, n1 = n0 + 1;
    if (n0 >= n) return;
    const bool has1 = (n1 < n);

    float a0[8], a1[8];
    float sl0 = g_dinv[n0]; sl0 *= sl0;
    scale8(g_hh[(long)n0 * 16 + sub], sl0, a0);
    int o0 = g_off[n0], c0 = g_cnt[n0];
    int o1 = 0, c1 = 0;
    if (has1) {
        float sl1 = g_dinv[n1]; sl1 *= sl1;
        scale8(g_hh[(long)n1 * 16 + sub], sl1, a1);
        o1 = g_off[n1]; c1 = g_cnt[n1];
    }

    const int cmin = c0 < c1 ? c0 : c1;
#pragma unroll 4
    for (int k = 0; k < cmin; k++) {
        int2 e0 = g_csr[o0 + k];
        int2 e1 = g_csr[o1 + k];
        uint4 r0 = g_hh[(long)e0.x * 16 + sub];
        uint4 r1 = g_hh[(long)e1.x * 16 + sub];
        fma8(r0, __int_as_float(e0.y), a0);
        fma8(r1, __int_as_float(e1.y), a1);
    }
#pragma unroll 4
    for (int k = cmin; k < c0; k++) {
        int2 e = g_csr[o0 + k];
        fma8(g_hh[(long)e.x * 16 + sub], __int_as_float(e.y), a0);
    }
#pragma unroll 4
    for (int k = cmin; k < c1; k++) {
        int2 e = g_csr[o1 + k];
        fma8(g_hh[(long)e.x * 16 + sub], __int_as_float(e.y), a1);
    }

    epilogue128(a0, bias, sub, n0);
    if (has1) epilogue128(a1, bias, sub, n1);
}

// ---------------- gather F=64 (final, fp32 out): 8-lane group, TWO nodes ----------------
__global__ void __launch_bounds__(256) k_gather_h64(const float* __restrict__ bias,
                                                    float* __restrict__ outp, int n) {
    const int gt  = blockIdx.x * blockDim.x + threadIdx.x;
    const int grp = gt >> 3;
    const int sub = gt & 7;              // lane owns features 8*sub .. 8*sub+7
    const int n0  = grp * 2, n1 = n0 + 1;
    if (n0 >= n) return;
    const bool has1 = (n1 < n);

    float a0[8], a1[8];
    float sl0 = g_dinv[n0]; sl0 *= sl0;
    scale8(g_hh[(long)n0 * 8 + sub], sl0, a0);
    int o0 = g_off[n0], c0 = g_cnt[n0];
    int o1 = 0, c1 = 0;
    if (has1) {
        float sl1 = g_dinv[n1]; sl1 *= sl1;
        scale8(g_hh[(long)n1 * 8 + sub], sl1, a1);
        o1 = g_off[n1]; c1 = g_cnt[n1];
    }

    const int cmin = c0 < c1 ? c0 : c1;
#pragma unroll 4
    for (int k = 0; k < cmin; k++) {
        int2 e0 = g_csr[o0 + k];
        int2 e1 = g_csr[o1 + k];
        uint4 r0 = g_hh[(long)e0.x * 8 + sub];
        uint4 r1 = g_hh[(long)e1.x * 8 + sub];
        fma8(r0, __int_as_float(e0.y), a0);
        fma8(r1, __int_as_float(e1.y), a1);
    }
#pragma unroll 4
    for (int k = cmin; k < c0; k++) {
        int2 e = g_csr[o0 + k];
        fma8(g_hh[(long)e.x * 8 + sub], __int_as_float(e.y), a0);
    }
#pragma unroll 4
    for (int k = cmin; k < c1; k++) {
        int2 e = g_csr[o1 + k];
        fma8(g_hh[(long)e.x * 8 + sub], __int_as_float(e.y), a1);
    }

    float4 b0 = *(const float4*)(bias + sub * 8);
    float4 b1 = *(const float4*)(bias + sub * 8 + 4);
    {
        float4 v0 = make_float4(a0[0] + b0.x, a0[1] + b0.y, a0[2] + b0.z, a0[3] + b0.w);
        float4 v1 = make_float4(a0[4] + b1.x, a0[5] + b1.y, a0[6] + b1.z, a0[7] + b1.w);
        *(float4*)(outp + (long)n0 * 64 + sub * 8)     = v0;
        *(float4*)(outp + (long)n0 * 64 + sub * 8 + 4) = v1;
    }
    if (has1) {
        float4 v0 = make_float4(a1[0] + b0.x, a1[1] + b0.y, a1[2] + b0.z, a1[3] + b0.w);
        float4 v1 = make_float4(a1[4] + b1.x, a1[5] + b1.y, a1[6] + b1.z, a1[7] + b1.w);
        *(float4*)(outp + (long)n1 * 64 + sub * 8)     = v0;
        *(float4*)(outp + (long)n1 * 64 + sub * 8 + 4) = v1;
    }
}

// ---------------- host launcher ----------------
extern "C" void kernel_launch(void* const* d_in, const int* in_sizes, int n_in,
                              void* d_out, int out_size) {
    const float* x  = (const float*)d_in[0];
    const void*  ei = d_in[1];
    const float* ew = (const float*)d_in[2];
    const float* W1 = (const float*)d_in[3];
    const float* b1 = (const float*)d_in[4];
    const float* W2 = (const float*)d_in[5];
    const float* b2 = (const float*)d_in[6];
    const float* W3 = (const float*)d_in[7];
    const float* b3 = (const float*)d_in[8];

    const int n = in_sizes[0] / KDIM;   // 50000
    const int E = in_sizes[2];          // 1600000
    float* outp = (float*)d_out;

    const int TB = 256;
    const int nb_nodes = (n + TB - 1) / TB;
    const int nb_edge2 = ((E + 1) / 2 + TB - 1) / TB;
    const int nchunk   = (n + 511) / 512;
    const int nprep    = (n * 16 + 5120 + TB - 1) / TB;
    const int gemm_blocks   = (n + 63) / 64;
    const int ngrp          = (n + 1) / 2;
    const int gat128_blocks = (ngrp * 16 + TB - 1) / TB;
    const int gat64_blocks  = (ngrp * 8 + TB - 1) / TB;

    // ---- fork: side stream runs prep + GEMM1 concurrently with CSR build ----
    cudaStream_t s1;
    cudaStreamCreateWithFlags(&s1, cudaStreamNonBlocking);
    cudaEvent_t e0, e1;
    cudaEventCreateWithFlags(&e0, cudaEventDisableTiming);
    cudaEventCreateWithFlags(&e1, cudaEventDisableTiming);

    cudaEventRecord(e0, 0);
    cudaStreamWaitEvent(s1, e0, 0);

    k_prep<<<nprep, TB, 0, s1>>>((const float4*)x, (const float4*)W1,
                                 (const float4*)W2, (const float4*)W3, n);
    k_hgemm<128><<<gemm_blocks, 256, 0, s1>>>(0, n);

    k_init<<<nb_nodes, TB>>>(ei, n);
    k_edge_deg<<<nb_edge2, TB>>>(ei, ew, E, n);
    k_scan<<<nchunk, 512>>>(n);
    k_edge_fill<<<nb_edge2, TB>>>(ei, ew, E);

    cudaEventRecord(e1, s1);
    cudaStreamWaitEvent(0, e1, 0);

    // ---- layer 1 gather ----
    k_gather_h<<<gat128_blocks, TB>>>(b1, n);

    // ---- layer 2 ----
    k_hgemm<128><<<gemm_blocks, 256>>>(2048, n);
    k_gather_h<<<gat128_blocks, TB>>>(b2, n);

    // ---- layer 3 ----
    k_hgemm<64><<<gemm_blocks, 256>>>(4096, n);
    k_gather_h64<<<gat64_blocks, TB>>>(b3, outp, n);

    cudaEventDestroy(e0);
    cudaEventDestroy(e1);
    cudaStreamDestroy(s1);
}

// round 17
// speedup vs baseline: 1.1285x; 1.1285x over previous
#include <cuda_runtime.h>
#include <cuda_fp16.h>
#include <mma.h>
using namespace nvcuda;

// ---------------- problem constants ----------------
#define NMAX 50000
#define EMAX 1600000
#define KDIM 128

// ---------------- device scratch ----------------
__device__ unsigned long long g_degc[NMAX];  // bits 44+: cnt, bits 0..43: ew-sum (2^-32 fixed)
__device__ float  g_dinv[NMAX];
__device__ int    g_cnt [NMAX];
__device__ int    g_off [NMAX];
__device__ int    g_rank[EMAX];
__device__ int2   g_csr [EMAX];              // (src, norm-as-bits), bucketed by dst
__device__ unsigned g_agg[256];              // lookback state: bit31 flag | aggregate
__device__ int    g_is64;
__device__ uint4  g_a16 [NMAX * KDIM / 8];   // fp16 activations (GEMM input)
__device__ uint4  g_hh  [NMAX * KDIM / 8];   // fp16 GEMM output (gather input)
__device__ uint4  g_w16 [5120];              // fp16 W1(2048) W2(2048) W3(1024)

// ---------------- fused init + dtype detect ----------------
__global__ void k_init(const void* __restrict__ ei, int n) {
    int i = blockIdx.x * blockDim.x + threadIdx.x;
    if (i < n) g_degc[i] = 0ULL;
    if (i < 256) g_agg[i] = 0u;
    if (i == 0) {
        const long long* p = (const long long*)ei;
        int ok = 1;
#pragma unroll
        for (int t = 0; t < 16; t++) {
            long long v = p[t];
            if (v < 0 || v >= (long long)n) ok = 0;
        }
        g_is64 = ok;
    }
}

// ---------------- fp32 -> fp16 conversion ----------------
__device__ inline uint4 pack8(float4 a, float4 b) {
    __half2 h0 = __floats2half2_rn(a.x, a.y), h1 = __floats2half2_rn(a.z, a.w);
    __half2 h2 = __floats2half2_rn(b.x, b.y), h3 = __floats2half2_rn(b.z, b.w);
    uint4 u;
    u.x = *(unsigned*)&h0; u.y = *(unsigned*)&h1;
    u.z = *(unsigned*)&h2; u.w = *(unsigned*)&h3;
    return u;
}

__global__ void k_prep(const float4* __restrict__ x,
                       const float4* __restrict__ W1,
                       const float4* __restrict__ W2,
                       const float4* __restrict__ W3, int n) {
    int i = blockIdx.x * blockDim.x + threadIdx.x;
    int nx = n * 16;
    if (i < nx) {
        g_a16[i] = pack8(x[2 * i], x[2 * i + 1]);
    } else {
        int j = i - nx;
        if (j < 5120) {
            const float4* src; int jj;
            if (j < 2048)      { src = W1; jj = j; }
            else if (j < 4096) { src = W2; jj = j - 2048; }
            else               { src = W3; jj = j - 4096; }
            g_w16[j] = pack8(src[2 * jj], src[2 * jj + 1]);
        }
    }
}

// ---------------- edge pass 1: 2 edges/thread, 64-bit packed atomic ----------------
__global__ void k_edge_deg(const void* __restrict__ ei,
                           const float* __restrict__ ew, int E, int n) {
    int e = (blockIdx.x * blockDim.x + threadIdx.x) * 2;
    if (e >= E) return;
    int s0, d0, s1 = -1, d1 = -1;
    bool two = (e + 1 < E);
    if (g_is64) {
        const long long* p = (const long long*)ei;
        s0 = (int)p[e]; d0 = (int)p[E + e];
        if (two) { s1 = (int)p[e + 1]; d1 = (int)p[E + e + 1]; }
    } else {
        const int* p = (const int*)ei;
        int2 sv = *(const int2*)(p + e);
        int2 dv = *(const int2*)(p + E + e);
        s0 = sv.x; d0 = dv.x;
        if (two) { s1 = sv.y; d1 = dv.y; }
    }
    float2 wv = two ? *(const float2*)(ew + e) : make_float2(ew[e], 0.f);
    int r0 = -1, r1 = -1;
    if ((unsigned)s0 < (unsigned)n && (unsigned)d0 < (unsigned)n) {
        unsigned long long fx = (unsigned long long)((double)wv.x * 4294967296.0);
        r0 = (int)(atomicAdd(&g_degc[d0], (1ULL << 44) | fx) >> 44);
    }
    if (two) {
        if ((unsigned)s1 < (unsigned)n && (unsigned)d1 < (unsigned)n) {
            unsigned long long fx = (unsigned long long)((double)wv.y * 4294967296.0);
            r1 = (int)(atomicAdd(&g_degc[d1], (1ULL << 44) | fx) >> 44);
        }
        *(int2*)(g_rank + e) = make_int2(r0, r1);
    } else {
        g_rank[e] = r0;
    }
}

// ---------------- single-kernel scan (decode degc -> dinv/cnt, lookback -> off) ----------------
__global__ void k_scan(int n) {
    __shared__ int s[512];
    __shared__ int base;
    const int t = threadIdx.x, b = blockIdx.x, i = b * 512 + t;
    int c = 0;
    if (i < n) {
        unsigned long long v = g_degc[i];
        float wsum = (float)((double)(v & ((1ULL << 44) - 1)) * (1.0 / 4294967296.0));
        g_dinv[i] = rsqrtf(wsum + 1.0f);          // +1 self-loop weight
        c = (int)(v >> 44);
        g_cnt[i] = c;
    }
    s[t] = c;
    __syncthreads();
    for (int st = 1; st < 512; st <<= 1) {
        int add = (t >= st) ? s[t - st] : 0;
        __syncthreads();
        s[t] += add;
        __syncthreads();
    }
    if (t == 511) atomicExch(&g_agg[b], 0x80000000u | (unsigned)s[511]);
    if (t == 0) base = 0;
    __syncthreads();
    int partial = 0;
    for (int j = t; j < b; j += 512) {
        unsigned v;
        do { v = atomicAdd(&g_agg[j], 0u); } while (!(v & 0x80000000u));
        partial += (int)(v & 0x7fffffffu);
    }
    if (partial) atomicAdd(&base, partial);
    __syncthreads();
    if (i < n) g_off[i] = base + s[t] - c;
}

// ---------------- edge pass 2: fill CSR (no atomics) ----------------
__global__ void k_edge_fill(const void* __restrict__ ei,
                            const float* __restrict__ ew, int E) {
    int e = (blockIdx.x * blockDim.x + threadIdx.x) * 2;
    if (e >= E) return;
    bool two = (e + 1 < E);
    int2 rr = two ? *(const int2*)(g_rank + e) : make_int2(g_rank[e], -1);
    int s0, d0, s1 = 0, d1 = 0;
    if (g_is64) {
        const long long* p = (const long long*)ei;
        s0 = (int)p[e]; d0 = (int)p[E + e];
        if (two) { s1 = (int)p[e + 1]; d1 = (int)p[E + e + 1]; }
    } else {
        const int* p = (const int*)ei;
        int2 sv = *(const int2*)(p + e);
        int2 dv = *(const int2*)(p + E + e);
        s0 = sv.x; d0 = dv.x; s1 = sv.y; d1 = dv.y;
    }
    float2 wv = two ? *(const float2*)(ew + e) : make_float2(ew[e], 0.f);
    if (rr.x >= 0) {
        float nrm = g_dinv[s0] * wv.x * g_dinv[d0];
        g_csr[g_off[d0] + rr.x] = make_int2(s0, __float_as_int(nrm));
    }
    if (two && rr.y >= 0) {
        float nrm = g_dinv[s1] * wv.y * g_dinv[d1];
        g_csr[g_off[d1] + rr.y] = make_int2(s1, __float_as_int(nrm));
    }
}

// ---------------- tensor-core GEMM: C[M,N] = A16[M,128] @ W16[128,N] ----------------
template<int N>
__global__ void __launch_bounds__(256)
k_hgemm(int woff_u4, int M) {
    constexpr int BM  = 64;
    constexpr int LDA = 136;
    constexpr int WN  = N / 2;
    constexpr int NT  = WN / 16;
    constexpr int ABYTES = BM * LDA * 2;
    constexpr int SBYTES = 8 * 16 * WN * 4;
    __shared__ __align__(16) char sraw[(ABYTES > SBYTES) ? ABYTES : SBYTES];
    __half (*As)[LDA] = (__half(*)[LDA])sraw;
    float*  stage     = (float*)sraw;

    const __half* Wg = (const __half*)g_w16 + (long)woff_u4 * 8;

    const int tid  = threadIdx.x;
    const int wid  = tid >> 5, lane = tid & 31;
    const int wrow = wid >> 1, wcol = wid & 1;
    const int rb   = blockIdx.x * BM;

    for (int i = tid; i < BM * 16; i += 256) {
        int r = i >> 4, c = i & 15;
        uint4 v = make_uint4(0u, 0u, 0u, 0u);
        if (rb + r < M) v = g_a16[(long)(rb + r) * 16 + c];
        *(uint4*)&As[r][c * 8] = v;
    }
    __syncthreads();

    wmma::fragment<wmma::accumulator, 16, 16, 16, float> acc[NT];
#pragma unroll
    for (int j = 0; j < NT; j++) wmma::fill_fragment(acc[j], 0.0f);

    wmma::fragment<wmma::matrix_a, 16, 16, 16, __half, wmma::row_major> af;
    wmma::fragment<wmma::matrix_b, 16, 16, 16, __half, wmma::row_major> bf;
#pragma unroll
    for (int k = 0; k < 8; k++) {
        wmma::load_matrix_sync(af, &As[wrow * 16][k * 16], LDA);
#pragma unroll
        for (int j = 0; j < NT; j++) {
            wmma::load_matrix_sync(bf, Wg + (long)(k * 16) * N + wcol * WN + j * 16, N);
            wmma::mma_sync(acc[j], af, bf, acc[j]);
        }
    }
    __syncthreads();

    float* st = stage + wid * 16 * WN;
#pragma unroll
    for (int j = 0; j < NT; j++)
        wmma::store_matrix_sync(st + j * 16, acc[j], WN, wmma::mem_row_major);
    __syncwarp();

    const int r0 = rb + wrow * 16;
    unsigned* outh = (unsigned*)g_hh;
    for (int i = lane; i < 16 * WN / 2; i += 32) {
        int r = (i * 2) / WN, c = (i * 2) % WN;
        int gr = r0 + r;
        if (gr < M) {
            __half2 h = __floats2half2_rn(st[r * WN + c], st[r * WN + c + 1]);
            outh[((long)gr * N + wcol * WN + c) >> 1] = *(unsigned*)&h;
        }
    }
}

// ---------------- fp16 row math helpers ----------------
__device__ inline void fma8(const uint4& hv, float nrm, float* a) {
    __half2 h0 = *(__half2*)&hv.x, h1 = *(__half2*)&hv.y;
    __half2 h2 = *(__half2*)&hv.z, h3 = *(__half2*)&hv.w;
    float2 f0 = __half22float2(h0), f1 = __half22float2(h1);
    float2 f2 = __half22float2(h2), f3 = __half22float2(h3);
    a[0] = fmaf(f0.x, nrm, a[0]); a[1] = fmaf(f0.y, nrm, a[1]);
    a[2] = fmaf(f1.x, nrm, a[2]); a[3] = fmaf(f1.y, nrm, a[3]);
    a[4] = fmaf(f2.x, nrm, a[4]); a[5] = fmaf(f2.y, nrm, a[5]);
    a[6] = fmaf(f3.x, nrm, a[6]); a[7] = fmaf(f3.y, nrm, a[7]);
}

__device__ inline void scale8(const uint4& hv, float sl, float* a) {
    __half2 h0 = *(__half2*)&hv.x, h1 = *(__half2*)&hv.y;
    __half2 h2 = *(__half2*)&hv.z, h3 = *(__half2*)&hv.w;
    float2 f0 = __half22float2(h0), f1 = __half22float2(h1);
    float2 f2 = __half22float2(h2), f3 = __half22float2(h3);
    a[0] = f0.x * sl; a[1] = f0.y * sl; a[2] = f1.x * sl; a[3] = f1.y * sl;
    a[4] = f2.x * sl; a[5] = f2.y * sl; a[6] = f3.x * sl; a[7] = f3.y * sl;
}

// ---------------- sparse aggregation, fp16, F=128: half-warp per node ----------------
__global__ void __launch_bounds__(256) k_gather_h(const float* __restrict__ bias, int n) {
    const int gt   = blockIdx.x * blockDim.x + threadIdx.x;
    const int node = gt >> 4;
    const int sub  = gt & 15;            // lane owns features 8*sub .. 8*sub+7
    if (node >= n) return;

    float di = g_dinv[node];
    float sl = di * di;

    float a[8];
    {
        uint4 sv = g_hh[(long)node * 16 + sub];
        scale8(sv, sl, a);
    }

    const int o = g_off[node];
    const int c = g_cnt[node];
#pragma unroll 8
    for (int k = 0; k < c; k++) {
        int2 sp = g_csr[o + k];                       // broadcast within half-warp
        float nrm = __int_as_float(sp.y);
        uint4 hv = g_hh[(long)sp.x * 16 + sub];       // 256B per half-warp
        fma8(hv, nrm, a);
    }

    float4 b0 = *(const float4*)(bias + sub * 8);
    float4 b1 = *(const float4*)(bias + sub * 8 + 4);
    float rx0 = fmaxf(a[0] + b0.x, 0.f), rx1 = fmaxf(a[1] + b0.y, 0.f);
    float rx2 = fmaxf(a[2] + b0.z, 0.f), rx3 = fmaxf(a[3] + b0.w, 0.f);
    float rx4 = fmaxf(a[4] + b1.x, 0.f), rx5 = fmaxf(a[5] + b1.y, 0.f);
    float rx6 = fmaxf(a[6] + b1.z, 0.f), rx7 = fmaxf(a[7] + b1.w, 0.f);
    __half2 p0 = __floats2half2_rn(rx0, rx1), p1 = __floats2half2_rn(rx2, rx3);
    __half2 p2 = __floats2half2_rn(rx4, rx5), p3 = __floats2half2_rn(rx6, rx7);
    uint4 u;
    u.x = *(unsigned*)&p0; u.y = *(unsigned*)&p1;
    u.z = *(unsigned*)&p2; u.w = *(unsigned*)&p3;
    g_a16[(long)node * 16 + sub] = u;
}

// ---------------- sparse aggregation, fp16, F=64 (final, fp32 out): 8 lanes/node ----------------
__global__ void __launch_bounds__(256) k_gather_h64(const float* __restrict__ bias,
                                                    float* __restrict__ outp, int n) {
    const int gt   = blockIdx.x * blockDim.x + threadIdx.x;
    const int node = gt >> 3;
    const int sub  = gt & 7;             // lane owns features 8*sub .. 8*sub+7
    if (node >= n) return;

    float di = g_dinv[node];
    float sl = di * di;

    float a[8];
    {
        uint4 sv = g_hh[(long)node * 8 + sub];
        scale8(sv, sl, a);
    }

    const int o = g_off[node];
    const int c = g_cnt[node];
#pragma unroll 8
    for (int k = 0; k < c; k++) {
        int2 sp = g_csr[o + k];
        float nrm = __int_as_float(sp.y);
        uint4 hv = g_hh[(long)sp.x * 8 + sub];
        fma8(hv, nrm, a);
    }

    float4 b0 = *(const float4*)(bias + sub * 8);
    float4 b1 = *(const float4*)(bias + sub * 8 + 4);
    float4 o0 = make_float4(a[0] + b0.x, a[1] + b0.y, a[2] + b0.z, a[3] + b0.w);
    float4 o1 = make_float4(a[4] + b1.x, a[5] + b1.y, a[6] + b1.z, a[7] + b1.w);
    *(float4*)(outp + (long)node * 64 + sub * 8)     = o0;
    *(float4*)(outp + (long)node * 64 + sub * 8 + 4) = o1;
}

// ---------------- host launcher ----------------
extern "C" void kernel_launch(void* const* d_in, const int* in_sizes, int n_in,
                              void* d_out, int out_size) {
    const float* x  = (const float*)d_in[0];
    const void*  ei = d_in[1];
    const float* ew = (const float*)d_in[2];
    const float* W1 = (const float*)d_in[3];
    const float* b1 = (const float*)d_in[4];
    const float* W2 = (const float*)d_in[5];
    const float* b2 = (const float*)d_in[6];
    const float* W3 = (const float*)d_in[7];
    const float* b3 = (const float*)d_in[8];

    const int n = in_sizes[0] / KDIM;   // 50000
    const int E = in_sizes[2];          // 1600000
    float* outp = (float*)d_out;

    const int TB = 256;
    const int nb_nodes = (n + TB - 1) / TB;
    const int nb_edge2 = ((E + 1) / 2 + TB - 1) / TB;
    const int nchunk   = (n + 511) / 512;
    const int nprep    = (n * 16 + 5120 + TB - 1) / TB;
    const int gemm_blocks   = (n + 63) / 64;
    const int gat128_blocks = (n * 16 + TB - 1) / TB;
    const int gat64_blocks  = (n * 8 + TB - 1) / TB;

    // ---- fork: side stream runs prep + GEMM1 concurrently with CSR build ----
    cudaStream_t s1;
    cudaStreamCreateWithFlags(&s1, cudaStreamNonBlocking);
    cudaEvent_t e0, e1;
    cudaEventCreateWithFlags(&e0, cudaEventDisableTiming);
    cudaEventCreateWithFlags(&e1, cudaEventDisableTiming);

    cudaEventRecord(e0, 0);
    cudaStreamWaitEvent(s1, e0, 0);

    k_prep<<<nprep, TB, 0, s1>>>((const float4*)x, (const float4*)W1,
                                 (const float4*)W2, (const float4*)W3, n);
    k_hgemm<128><<<gemm_blocks, 256, 0, s1>>>(0, n);

    k_init<<<nb_nodes, TB>>>(ei, n);
    k_edge_deg<<<nb_edge2, TB>>>(ei, ew, E, n);
    k_scan<<<nchunk, 512>>>(n);
    k_edge_fill<<<nb_edge2, TB>>>(ei, ew, E);

    cudaEventRecord(e1, s1);
    cudaStreamWaitEvent(0, e1, 0);

    // ---- layer 1 gather ----
    k_gather_h<<<gat128_blocks, TB>>>(b1, n);

    // ---- layer 2 ----
    k_hgemm<128><<<gemm_blocks, 256>>>(2048, n);
    k_gather_h<<<gat128_blocks, TB>>>(b2, n);

    // ---- layer 3 ----
    k_hgemm<64><<<gemm_blocks, 256>>>(4096, n);
    k_gather_h64<<<gat64_blocks, TB>>>(b3, outp, n);

    cudaEventDestroy(e0);
    cudaEventDestroy(e1);
    cudaStreamDestroy(s1);
}